// round 5
// baseline (speedup 1.0000x reference)
#include <cuda_runtime.h>

#define NN    32768
#define NB    64        // graphs
#define CIN   256
#define E     256
#define NSC   4
#define OS    64        // out per scale
#define NH    8
#define HD    32
#define BN_EPS 1e-5f

// ---------------- scratch (device globals: no allocation allowed) ----------
__device__ float g_h  [(size_t)NN * E];        // 32 MB
__device__ float g_qkv[(size_t)NN * 3 * E];    // 96 MB
__device__ float g_ctx[(size_t)NN * E];        // 32 MB
__device__ float g_att[(size_t)NN * E];        // 32 MB
__device__ int   g_counts[NB];
__device__ int   g_starts[NB];
__device__ int   g_maxM;
__device__ int   g_stride;                     // 1 = int32 batch, 2 = int64 batch
__device__ float g_psum  [256 * E];            // deterministic BN partials
__device__ float g_psumsq[256 * E];
__device__ float g_bnscale[E];
__device__ float g_bnshift[E];

// ---------------- batch bookkeeping ----------------------------------------
// The reference casts batch with jnp.astype(int64); under default JAX config
// (x64 disabled) this silently yields int32. Detect the element width by
// scanning odd 32-bit words: for little-endian int64 values < 2^32 they are
// all zero; for int32 data they are batch[odd] which (sorted ids over 64
// graphs) are mostly nonzero. Reads stay within 4*NN bytes either way.
__global__ void k_detect(const int* __restrict__ b32)
{
    __shared__ int any;
    if (threadIdx.x == 0) any = 0;
    __syncthreads();
    int loc = 0;
    for (int i = threadIdx.x; i < NN / 2; i += blockDim.x)
        if (b32[2 * i + 1] != 0) loc = 1;
    if (loc) atomicExch(&any, 1);
    __syncthreads();
    if (threadIdx.x == 0) {
        g_stride = any ? 1 : 2;
        for (int b = 0; b < NB; b++) g_counts[b] = 0;
    }
}

__global__ void k_hist(const int* __restrict__ b32)
{
    __shared__ int hc[NB];
    int t = threadIdx.x;
    if (t < NB) hc[t] = 0;
    __syncthreads();
    int n = blockIdx.x * blockDim.x + t;
    int v = b32[(size_t)n * g_stride] & (NB - 1);   // clamp for safety
    atomicAdd(&hc[v], 1);
    __syncthreads();
    if (t < NB) atomicAdd(&g_counts[t], hc[t]);
}

__global__ void k_scan()
{
    // B=64 -> single thread is fine
    int run = 0, mx = 0;
    for (int b = 0; b < NB; b++) {
        g_starts[b] = run;
        int c = g_counts[b];
        run += c;
        if (c > mx) mx = c;
    }
    g_maxM = mx;
}

// ---------------- GEMM 1: per-scale linear on (x + spectral) ---------------
// h[n, s*64+o] = sum_i (x[n,i] + spectral[s,n,i]) * Ws[s,i,o] + bs[s,o]
// grid: (NN/64, 1, NSC), block: 256 (16x16, 4x4 micro-tile)
__global__ void k_gemm_scale(const float* __restrict__ x,
                             const float* __restrict__ spec,
                             const float* __restrict__ Ws,
                             const float* __restrict__ bs)
{
    __shared__ float As[16][65];
    __shared__ float Bs[16][65];
    const int s  = blockIdx.z;
    const int m0 = blockIdx.x * 64;
    const int tid = threadIdx.x;
    const int tx = tid & 15, ty = tid >> 4;

    const float* xb = x    + (size_t)m0 * CIN;
    const float* sb = spec + (size_t)s * NN * CIN + (size_t)m0 * CIN;
    const float* Wb = Ws   + (size_t)s * CIN * OS;

    const int lr = tid >> 2;          // 0..63 row within tile
    const int lk = (tid & 3) * 4;     // k offset
    const int bk = tid >> 4;          // 0..15
    const int bo = (tid & 15) * 4;    // 0..60

    float acc[4][4] = {};

    for (int k0 = 0; k0 < CIN; k0 += 16) {
        float4 a  = *(const float4*)(xb + (size_t)lr * CIN + k0 + lk);
        float4 a2 = *(const float4*)(sb + (size_t)lr * CIN + k0 + lk);
        As[lk + 0][lr] = a.x + a2.x;
        As[lk + 1][lr] = a.y + a2.y;
        As[lk + 2][lr] = a.z + a2.z;
        As[lk + 3][lr] = a.w + a2.w;
        float4 b = *(const float4*)(Wb + (size_t)(k0 + bk) * OS + bo);
        Bs[bk][bo + 0] = b.x;
        Bs[bk][bo + 1] = b.y;
        Bs[bk][bo + 2] = b.z;
        Bs[bk][bo + 3] = b.w;
        __syncthreads();
#pragma unroll
        for (int k = 0; k < 16; k++) {
            float av[4], bv[4];
#pragma unroll
            for (int i = 0; i < 4; i++) av[i] = As[k][ty * 4 + i];
#pragma unroll
            for (int j = 0; j < 4; j++) bv[j] = Bs[k][tx * 4 + j];
#pragma unroll
            for (int i = 0; i < 4; i++)
#pragma unroll
                for (int j = 0; j < 4; j++) acc[i][j] += av[i] * bv[j];
        }
        __syncthreads();
    }
#pragma unroll
    for (int i = 0; i < 4; i++) {
        int m = m0 + ty * 4 + i;
#pragma unroll
        for (int j = 0; j < 4; j++) {
            int o = tx * 4 + j;
            g_h[(size_t)m * E + s * OS + o] = acc[i][j] + bs[s * OS + o];
        }
    }
}

// ---------------- GEMM body: C = A[NN,256] * W^T + bias --------------------
// W row-major [Nc, 256]; tile (m0, n0) from blockIdx, 64x64
__device__ __forceinline__ void gemm_wt_body(const float* __restrict__ A,
                                             const float* __restrict__ W,
                                             const float* __restrict__ bias,
                                             float* __restrict__ C, int ldc)
{
    __shared__ float As[16][65];
    __shared__ float Bs[16][65];
    const int m0 = blockIdx.x * 64;
    const int n0 = blockIdx.y * 64;
    const int tid = threadIdx.x;
    const int tx = tid & 15, ty = tid >> 4;
    const int lr = tid >> 2;
    const int lk = (tid & 3) * 4;

    float acc[4][4] = {};

    for (int k0 = 0; k0 < 256; k0 += 16) {
        float4 a = *(const float4*)(A + (size_t)(m0 + lr) * 256 + k0 + lk);
        As[lk + 0][lr] = a.x;
        As[lk + 1][lr] = a.y;
        As[lk + 2][lr] = a.z;
        As[lk + 3][lr] = a.w;
        float4 b = *(const float4*)(W + (size_t)(n0 + lr) * 256 + k0 + lk);
        Bs[lk + 0][lr] = b.x;
        Bs[lk + 1][lr] = b.y;
        Bs[lk + 2][lr] = b.z;
        Bs[lk + 3][lr] = b.w;
        __syncthreads();
#pragma unroll
        for (int k = 0; k < 16; k++) {
            float av[4], bv[4];
#pragma unroll
            for (int i = 0; i < 4; i++) av[i] = As[k][ty * 4 + i];
#pragma unroll
            for (int j = 0; j < 4; j++) bv[j] = Bs[k][tx * 4 + j];
#pragma unroll
            for (int i = 0; i < 4; i++)
#pragma unroll
                for (int j = 0; j < 4; j++) acc[i][j] += av[i] * bv[j];
        }
        __syncthreads();
    }
#pragma unroll
    for (int i = 0; i < 4; i++) {
        int m = m0 + ty * 4 + i;
#pragma unroll
        for (int j = 0; j < 4; j++) {
            int n = n0 + tx * 4 + j;
            C[(size_t)m * ldc + n] = acc[i][j] + bias[n];
        }
    }
}

__global__ void k_gemm_qkv(const float* __restrict__ W, const float* __restrict__ bias)
{
    gemm_wt_body(g_h, W, bias, g_qkv, 3 * E);
}

__global__ void k_gemm_out(const float* __restrict__ W, const float* __restrict__ bias)
{
    gemm_wt_body(g_ctx, W, bias, g_att, E);
}

// ---------------- attention: per (graph, head), online softmax -------------
// Padding semantics of the reference (no key-padding mask): each graph is
// padded to M = max count; padded rows have h=0 -> k_pad = b_in[E:2E],
// v_pad = b_in[2E:3E]. Fold (M-c) copies of that key analytically.
__global__ void k_attn(const float* __restrict__ b_in)
{
    __shared__ float Kt[64][32];
    __shared__ float Vt[64][32];
    __shared__ float kp[32], vp[32];

    const int b = blockIdx.x;
    const int h = blockIdx.y;
    const int tid = threadIdx.x;          // 128 threads
    const int c = g_counts[b];
    const int start = g_starts[b];
    const int M = g_maxM;
    const float qscale = 0.17677669529663687f; // 1/sqrt(32)

    if (tid < 32) {
        kp[tid] = b_in[E     + h * HD + tid];
        vp[tid] = b_in[2 * E + h * HD + tid];
    }
    __syncthreads();

    for (int q0 = 0; q0 < c; q0 += 128) {
        const int qi = q0 + tid;
        const bool valid = qi < c;
        float qv[HD];
        if (valid) {
            const float* qp = g_qkv + (size_t)(start + qi) * 768 + h * HD;
#pragma unroll
            for (int d = 0; d < HD; d++) qv[d] = qp[d] * qscale;
        }
        float m = -1e9f, l = 0.f, acc[HD];
#pragma unroll
        for (int d = 0; d < HD; d++) acc[d] = 0.f;

        for (int kb = 0; kb < c; kb += 64) {
            const int nk = min(64, c - kb);
            __syncthreads();
            for (int e = tid; e < nk * 32; e += 128) {
                int j = e >> 5, d = e & 31;
                size_t base = (size_t)(start + kb + j) * 768 + h * HD + d;
                Kt[j][d] = g_qkv[base + E];
                Vt[j][d] = g_qkv[base + 2 * E];
            }
            __syncthreads();
            if (valid) {
                for (int j = 0; j < nk; j++) {
                    float s = 0.f;
#pragma unroll
                    for (int d = 0; d < HD; d++) s += qv[d] * Kt[j][d];
                    float mn = fmaxf(m, s);
                    float corr = __expf(m - mn);
                    float w = __expf(s - mn);
                    l = l * corr + w;
#pragma unroll
                    for (int d = 0; d < HD; d++) acc[d] = acc[d] * corr + w * Vt[j][d];
                    m = mn;
                }
            }
        }

        if (valid) {
            int npad = M - c;
            if (npad > 0) {
                float s = 0.f;
#pragma unroll
                for (int d = 0; d < HD; d++) s += qv[d] * kp[d];
                float mn = fmaxf(m, s);
                float corr = __expf(m - mn);
                float w = __expf(s - mn) * (float)npad;
                l = l * corr + w;
#pragma unroll
                for (int d = 0; d < HD; d++) acc[d] = acc[d] * corr + w * vp[d];
                m = mn;
            }
            float inv = 1.f / l;
            float* o = g_ctx + (size_t)(start + qi) * E + h * HD;
#pragma unroll
            for (int d = 0; d < HD; d++) o[d] = acc[d] * inv;
        }
    }
}

// ---------------- BatchNorm (training stats) + ReLU -------------------------
// Deterministic two-stage column reduction (no float atomics).
__global__ void k_bn_stats()
{
    const int ch = threadIdx.x;           // 256 channels
    const int r0 = blockIdx.x * 128;      // 256 blocks x 128 rows
    float s = 0.f, s2 = 0.f;
    for (int r = 0; r < 128; r++) {
        float v = g_att[(size_t)(r0 + r) * E + ch];
        s += v;
        s2 += v * v;
    }
    g_psum  [blockIdx.x * E + ch] = s;
    g_psumsq[blockIdx.x * E + ch] = s2;
}

__global__ void k_bn_finalize(const float* __restrict__ gamma,
                              const float* __restrict__ beta)
{
    const int ch = threadIdx.x;
    float s = 0.f, s2 = 0.f;
    for (int p = 0; p < 256; p++) {
        s  += g_psum  [p * E + ch];
        s2 += g_psumsq[p * E + ch];
    }
    float mean = s / (float)NN;
    float var  = s2 / (float)NN - mean * mean;
    float sc = rsqrtf(var + BN_EPS) * gamma[ch];
    g_bnscale[ch] = sc;
    g_bnshift[ch] = beta[ch] - mean * sc;
}

__global__ void k_bn_apply(float* __restrict__ out)
{
    size_t i4 = (size_t)blockIdx.x * blockDim.x + threadIdx.x;   // float4 index
    size_t idx = i4 * 4;
    int ch = (int)(idx & (E - 1));
    float4 v = *(const float4*)(g_att + idx);
    float4 r;
    r.x = fmaxf(v.x * g_bnscale[ch + 0] + g_bnshift[ch + 0], 0.f);
    r.y = fmaxf(v.y * g_bnscale[ch + 1] + g_bnshift[ch + 1], 0.f);
    r.z = fmaxf(v.z * g_bnscale[ch + 2] + g_bnshift[ch + 2], 0.f);
    r.w = fmaxf(v.w * g_bnscale[ch + 3] + g_bnshift[ch + 3], 0.f);
    *(float4*)(out + idx) = r;
}

// ---------------- launch -----------------------------------------------------
extern "C" void kernel_launch(void* const* d_in, const int* in_sizes, int n_in,
                              void* d_out, int out_size)
{
    const float* x        = (const float*)d_in[0];
    const float* spectral = (const float*)d_in[1];
    const float* Ws       = (const float*)d_in[2];
    const float* bs       = (const float*)d_in[3];
    const float* W_in     = (const float*)d_in[4];
    const float* b_in     = (const float*)d_in[5];
    const float* W_out    = (const float*)d_in[6];
    const float* b_out    = (const float*)d_in[7];
    const float* gamma    = (const float*)d_in[8];
    const float* beta     = (const float*)d_in[9];
    const int*   batch32  = (const int*)d_in[10];   // width detected at runtime
    float* out = (float*)d_out;

    k_detect<<<1, 256>>>(batch32);
    k_hist<<<NN / 256, 256>>>(batch32);
    k_scan<<<1, 1>>>();

    k_gemm_scale<<<dim3(NN / 64, 1, NSC), 256>>>(x, spectral, Ws, bs);
    k_gemm_qkv<<<dim3(NN / 64, 12), 256>>>(W_in, b_in);
    k_attn<<<dim3(NB, NH), 128>>>(b_in);
    k_gemm_out<<<dim3(NN / 64, 4), 256>>>(W_out, b_out);

    k_bn_stats<<<256, 256>>>();
    k_bn_finalize<<<1, 256>>>(gamma, beta);
    k_bn_apply<<<(NN * E / 4) / 256, 256>>>(out);
}

// round 9
// speedup vs baseline: 1.6754x; 1.6754x over previous
#include <cuda_runtime.h>
#include <cuda_bf16.h>

#define NN 32768
#define NB 64
#define E  256
#define NSC 4
#define NH 8
#define HD 32
#define BN_EPS 1e-5f

__device__ float g_h  [(size_t)NN * E];
__device__ float g_qkv[(size_t)NN * 3 * E];
__device__ float g_ctx[(size_t)NN * E];
__device__ float g_att[(size_t)NN * E];
__device__ int   g_counts[NB], g_starts[NB], g_maxM, g_stride;
__device__ float g_psum[256 * E], g_psumsq[256 * E];
__device__ float g_bnscale[E], g_bnshift[E];
#define W_TOT (196608 + 65536 + 65536)
__device__ float g_Whi[W_TOT], g_Wlo[W_TOT];

__device__ __forceinline__ float tf32r(float x)
{ float r; asm("cvt.rna.tf32.f32 %0, %1;" : "=f"(r) : "f"(x)); return r; }
__device__ __forceinline__ unsigned fu(float x) { return __float_as_uint(x); }
__device__ __forceinline__ float b2f(__nv_bfloat16 x) { return __bfloat162float(x); }
__device__ __forceinline__ void mma8(float* c, const unsigned* a, unsigned b0, unsigned b1)
{
    asm volatile("mma.sync.aligned.m16n8k8.row.col.f32.tf32.tf32.f32 "
                 "{%0,%1,%2,%3}, {%4,%5,%6,%7}, {%8,%9}, {%0,%1,%2,%3};"
                 : "+f"(c[0]), "+f"(c[1]), "+f"(c[2]), "+f"(c[3])
                 : "r"(a[0]), "r"(a[1]), "r"(a[2]), "r"(a[3]), "r"(b0), "r"(b1));
}

// ---- batch bookkeeping (int32 vs int64 sniffing) ----
__global__ void k_detect(const int* __restrict__ b32)
{
    __shared__ int any;
    if (threadIdx.x == 0) any = 0;
    __syncthreads();
    int loc = 0;
    for (int i = threadIdx.x; i < NN / 2; i += blockDim.x)
        if (b32[2 * i + 1] != 0) loc = 1;
    if (loc) atomicExch(&any, 1);
    __syncthreads();
    if (threadIdx.x == 0) {
        g_stride = any ? 1 : 2;
        for (int b = 0; b < NB; b++) g_counts[b] = 0;
    }
}
__global__ void k_hist(const int* __restrict__ b32)
{
    __shared__ int hc[NB];
    int t = threadIdx.x;
    if (t < NB) hc[t] = 0;
    __syncthreads();
    int n = blockIdx.x * blockDim.x + t;
    atomicAdd(&hc[b32[(size_t)n * g_stride] & (NB - 1)], 1);
    __syncthreads();
    if (t < NB) atomicAdd(&g_counts[t], hc[t]);
}
__global__ void k_scan()
{
    int run = 0, mx = 0;
    for (int b = 0; b < NB; b++) {
        g_starts[b] = run;
        int c = g_counts[b];
        run += c;
        if (c > mx) mx = c;
    }
    g_maxM = mx;
}

// ---- weight split prep: [W_in | W_out | Ws^T(s,o,k)] ----
__global__ void k_split_w(const float* __restrict__ W_in, const float* __restrict__ W_out,
                          const float* __restrict__ Ws)
{
    int i = blockIdx.x * blockDim.x + threadIdx.x;
    if (i >= W_TOT) return;
    float w;
    if (i < 196608) w = W_in[i];
    else if (i < 262144) w = W_out[i - 196608];
    else {
        int j = i - 262144, s = j >> 14, rem = j & 16383;
        w = Ws[s * 16384 + (rem & 255) * 64 + (rem >> 8)];
    }
    float hi = tf32r(w);
    g_Whi[i] = hi;
    g_Wlo[i] = w - hi;
}

// ---- tensor-core GEMM body: C[NN,NTOT] = A[NN,256] * W^T + bias ----
// block 64m x 128n, 8 warps (4 wm x 2 wn), warp tile 16x64; k-chunks of 32.
// NOTE: device-global pointers are bound by wrapper kernels IN DEVICE CODE —
// passing __device__ symbols from host was the round-7/8 failure.
template<int NTOT>
__device__ __forceinline__ void gemm_tc_body(
    const float* __restrict__ A, const float* __restrict__ Whi,
    const float* __restrict__ Wlo, const float* __restrict__ bias,
    float* __restrict__ C)
{
    __shared__ float         Ah[64][36];
    __shared__ __nv_bfloat16 Al[64][36];
    __shared__ float         Bh[128][36];
    __shared__ __nv_bfloat16 Bl[128][36];
    const int tid = threadIdx.x, wid = tid >> 5, lane = tid & 31;
    const int g = lane >> 2, t4 = lane & 3, wm = wid >> 1, wn = wid & 1;
    const int m0 = blockIdx.x * 64, n0 = blockIdx.y * 128;

    float acc[8][4] = {};
    for (int ch = 0; ch < 8; ch++) {
        __syncthreads();
        for (int i = tid; i < 512; i += 256) {          // A chunk 64x32
            int r = i >> 3, c4 = (i & 7) << 2;
            float4 v = *(const float4*)(A + (size_t)(m0 + r) * 256 + ch * 32 + c4);
            float h0 = tf32r(v.x), h1 = tf32r(v.y), h2 = tf32r(v.z), h3 = tf32r(v.w);
            Ah[r][c4] = h0; Ah[r][c4 + 1] = h1; Ah[r][c4 + 2] = h2; Ah[r][c4 + 3] = h3;
            Al[r][c4] = __float2bfloat16_rn(v.x - h0);
            Al[r][c4 + 1] = __float2bfloat16_rn(v.y - h1);
            Al[r][c4 + 2] = __float2bfloat16_rn(v.z - h2);
            Al[r][c4 + 3] = __float2bfloat16_rn(v.w - h3);
        }
        for (int i = tid; i < 1024; i += 256) {         // B chunk 128x32
            int r = i >> 3, c4 = (i & 7) << 2;
            size_t go = (size_t)(n0 + r) * 256 + ch * 32 + c4;
            float4 h = *(const float4*)(Whi + go);
            float4 l = *(const float4*)(Wlo + go);
            Bh[r][c4] = h.x; Bh[r][c4 + 1] = h.y; Bh[r][c4 + 2] = h.z; Bh[r][c4 + 3] = h.w;
            Bl[r][c4] = __float2bfloat16_rn(l.x);
            Bl[r][c4 + 1] = __float2bfloat16_rn(l.y);
            Bl[r][c4 + 2] = __float2bfloat16_rn(l.z);
            Bl[r][c4 + 3] = __float2bfloat16_rn(l.w);
        }
        __syncthreads();
#pragma unroll
        for (int kk = 0; kk < 4; kk++) {
            const int k = kk * 8, ra = 16 * wm + g;
            unsigned ah[4], al[4];
            ah[0] = fu(Ah[ra][k + t4]);     ah[1] = fu(Ah[ra + 8][k + t4]);
            ah[2] = fu(Ah[ra][k + t4 + 4]); ah[3] = fu(Ah[ra + 8][k + t4 + 4]);
            al[0] = fu(b2f(Al[ra][k + t4]));     al[1] = fu(b2f(Al[ra + 8][k + t4]));
            al[2] = fu(b2f(Al[ra][k + t4 + 4])); al[3] = fu(b2f(Al[ra + 8][k + t4 + 4]));
#pragma unroll
            for (int ni = 0; ni < 8; ni++) {
                int n = 64 * wn + 8 * ni + g;
                unsigned bh0 = fu(Bh[n][k + t4]), bh1 = fu(Bh[n][k + t4 + 4]);
                mma8(acc[ni], ah, bh0, bh1);
                mma8(acc[ni], ah, fu(b2f(Bl[n][k + t4])), fu(b2f(Bl[n][k + t4 + 4])));
                mma8(acc[ni], al, bh0, bh1);
            }
        }
    }
    const int r1 = m0 + 16 * wm + g;
#pragma unroll
    for (int ni = 0; ni < 8; ni++) {
        int n = n0 + 64 * wn + 8 * ni + 2 * t4;
        float b0 = bias[n], b1 = bias[n + 1];
        *(float2*)(C + (size_t)r1 * NTOT + n)       = make_float2(acc[ni][0] + b0, acc[ni][1] + b1);
        *(float2*)(C + (size_t)(r1 + 8) * NTOT + n) = make_float2(acc[ni][2] + b0, acc[ni][3] + b1);
    }
}

__global__ void __launch_bounds__(256) k_gemm_qkv_tc(const float* __restrict__ bias)
{ gemm_tc_body<768>(g_h, g_Whi, g_Wlo, bias, g_qkv); }

__global__ void __launch_bounds__(256) k_gemm_out_tc(const float* __restrict__ bias)
{ gemm_tc_body<256>(g_ctx, g_Whi + 196608, g_Wlo + 196608, bias, g_att); }

// ---- scale GEMM: h[:, s*64+o] = (x + spec[s]) * WsT[s] + bs ----
__global__ void __launch_bounds__(256) k_gemm_scale_tc(
    const float* __restrict__ x, const float* __restrict__ spec,
    const float* __restrict__ bs)
{
    __shared__ float         Ah[64][36];
    __shared__ __nv_bfloat16 Al[64][36];
    __shared__ float         Bh[64][36];
    __shared__ __nv_bfloat16 Bl[64][36];
    const int tid = threadIdx.x, wid = tid >> 5, lane = tid & 31;
    const int g = lane >> 2, t4 = lane & 3, wm = wid >> 1, wn = wid & 1;
    const int m0 = blockIdx.x * 64;

    for (int s = 0; s < NSC; s++) {
        const float* sb = spec + (size_t)s * NN * 256;
        const float* Wsh = g_Whi + 262144 + s * 16384;
        const float* Wsl = g_Wlo + 262144 + s * 16384;
        float acc[4][4] = {};
        for (int ch = 0; ch < 8; ch++) {
            __syncthreads();
            for (int i = tid; i < 512; i += 256) {
                int r = i >> 3, c4 = (i & 7) << 2;
                size_t go = (size_t)(m0 + r) * 256 + ch * 32 + c4;
                float4 a = *(const float4*)(x + go);
                float4 b = *(const float4*)(sb + go);
                a.x += b.x; a.y += b.y; a.z += b.z; a.w += b.w;
                float h0 = tf32r(a.x), h1 = tf32r(a.y), h2 = tf32r(a.z), h3 = tf32r(a.w);
                Ah[r][c4] = h0; Ah[r][c4 + 1] = h1; Ah[r][c4 + 2] = h2; Ah[r][c4 + 3] = h3;
                Al[r][c4] = __float2bfloat16_rn(a.x - h0);
                Al[r][c4 + 1] = __float2bfloat16_rn(a.y - h1);
                Al[r][c4 + 2] = __float2bfloat16_rn(a.z - h2);
                Al[r][c4 + 3] = __float2bfloat16_rn(a.w - h3);
            }
            for (int i = tid; i < 512; i += 256) {
                int r = i >> 3, c4 = (i & 7) << 2;
                size_t go = (size_t)r * 256 + ch * 32 + c4;
                float4 h = *(const float4*)(Wsh + go);
                float4 l = *(const float4*)(Wsl + go);
                Bh[r][c4] = h.x; Bh[r][c4 + 1] = h.y; Bh[r][c4 + 2] = h.z; Bh[r][c4 + 3] = h.w;
                Bl[r][c4] = __float2bfloat16_rn(l.x);
                Bl[r][c4 + 1] = __float2bfloat16_rn(l.y);
                Bl[r][c4 + 2] = __float2bfloat16_rn(l.z);
                Bl[r][c4 + 3] = __float2bfloat16_rn(l.w);
            }
            __syncthreads();
#pragma unroll
            for (int kk = 0; kk < 4; kk++) {
                const int k = kk * 8, ra = 16 * wm + g;
                unsigned ah[4], al[4];
                ah[0] = fu(Ah[ra][k + t4]);     ah[1] = fu(Ah[ra + 8][k + t4]);
                ah[2] = fu(Ah[ra][k + t4 + 4]); ah[3] = fu(Ah[ra + 8][k + t4 + 4]);
                al[0] = fu(b2f(Al[ra][k + t4]));     al[1] = fu(b2f(Al[ra + 8][k + t4]));
                al[2] = fu(b2f(Al[ra][k + t4 + 4])); al[3] = fu(b2f(Al[ra + 8][k + t4 + 4]));
#pragma unroll
                for (int ni = 0; ni < 4; ni++) {
                    int n = 32 * wn + 8 * ni + g;
                    unsigned bh0 = fu(Bh[n][k + t4]), bh1 = fu(Bh[n][k + t4 + 4]);
                    mma8(acc[ni], ah, bh0, bh1);
                    mma8(acc[ni], ah, fu(b2f(Bl[n][k + t4])), fu(b2f(Bl[n][k + t4 + 4])));
                    mma8(acc[ni], al, bh0, bh1);
                }
            }
        }
        const int r1 = m0 + 16 * wm + g;
#pragma unroll
        for (int ni = 0; ni < 4; ni++) {
            int col = 32 * wn + 8 * ni + 2 * t4, n = s * 64 + col;
            float b0 = bs[n], b1 = bs[n + 1];
            *(float2*)(g_h + (size_t)r1 * 256 + n)       = make_float2(acc[ni][0] + b0, acc[ni][1] + b1);
            *(float2*)(g_h + (size_t)(r1 + 8) * 256 + n) = make_float2(acc[ni][2] + b0, acc[ni][3] + b1);
        }
        __syncthreads();
    }
}

// ---- flash attention (tf32 mma): 128 threads, Q tile 64, K/V tile 32 ----
// Pad keys of the reference (no key-padding mask) folded analytically with
// multiplicity (maxM - c).
__global__ void __launch_bounds__(128) k_attn_tc(const float* __restrict__ b_in)
{
    __shared__ float         Qh[64][36];
    __shared__ __nv_bfloat16 Ql[64][36];
    __shared__ float         Kh[32][36];
    __shared__ __nv_bfloat16 Kl[32][36];
    __shared__ float         Vh[32][36];   // d-major: Vh[d][key]
    __shared__ __nv_bfloat16 Vl[32][36];
    __shared__ float         Pm[4][16][36];
    __shared__ __nv_bfloat16 Pl[4][16][36];
    __shared__ float         kp[32], vp[32];

    const int b = blockIdx.x, h = blockIdx.y;
    const int tid = threadIdx.x, wid = tid >> 5, lane = tid & 31;
    const int g = lane >> 2, t4 = lane & 3;
    const int c = g_counts[b], start = g_starts[b];
    const float npadf = (float)(g_maxM - c);
    const float qs = 0.17677669529663687f;

    if (tid < 32) { kp[tid] = b_in[E + h * HD + tid]; vp[tid] = b_in[2 * E + h * HD + tid]; }

    for (int q0 = 0; q0 < c; q0 += 64) {
        __syncthreads();
        for (int i = tid; i < 512; i += 128) {        // Q tile 64x32
            int r = i >> 3, c4 = (i & 7) << 2, row = q0 + r;
            float4 v = make_float4(0.f, 0.f, 0.f, 0.f);
            if (row < c) v = *(const float4*)(g_qkv + (size_t)(start + row) * 768 + h * HD + c4);
            v.x *= qs; v.y *= qs; v.z *= qs; v.w *= qs;
            float h0 = tf32r(v.x), h1 = tf32r(v.y), h2 = tf32r(v.z), h3 = tf32r(v.w);
            Qh[r][c4] = h0; Qh[r][c4 + 1] = h1; Qh[r][c4 + 2] = h2; Qh[r][c4 + 3] = h3;
            Ql[r][c4] = __float2bfloat16_rn(v.x - h0);
            Ql[r][c4 + 1] = __float2bfloat16_rn(v.y - h1);
            Ql[r][c4 + 2] = __float2bfloat16_rn(v.z - h2);
            Ql[r][c4 + 3] = __float2bfloat16_rn(v.w - h3);
        }
        float m1 = -1e30f, m2 = -1e30f, l1 = 0.f, l2 = 0.f;
        float acc[4][4] = {};

        for (int kb = 0; kb < c; kb += 32) {
            __syncthreads();
            for (int i = tid; i < 256; i += 128) {    // K/V chunk 32x32
                int r = i >> 3, c4 = (i & 7) << 2, key = kb + r;
                float4 kv = make_float4(0.f, 0.f, 0.f, 0.f);
                float4 vv = make_float4(0.f, 0.f, 0.f, 0.f);
                if (key < c) {
                    size_t base = (size_t)(start + key) * 768 + h * HD + c4;
                    kv = *(const float4*)(g_qkv + base + E);
                    vv = *(const float4*)(g_qkv + base + 2 * E);
                }
                float h0 = tf32r(kv.x), h1 = tf32r(kv.y), h2 = tf32r(kv.z), h3 = tf32r(kv.w);
                Kh[r][c4] = h0; Kh[r][c4 + 1] = h1; Kh[r][c4 + 2] = h2; Kh[r][c4 + 3] = h3;
                Kl[r][c4] = __float2bfloat16_rn(kv.x - h0);
                Kl[r][c4 + 1] = __float2bfloat16_rn(kv.y - h1);
                Kl[r][c4 + 2] = __float2bfloat16_rn(kv.z - h2);
                Kl[r][c4 + 3] = __float2bfloat16_rn(kv.w - h3);
                float v0 = tf32r(vv.x), v1 = tf32r(vv.y), v2 = tf32r(vv.z), v3 = tf32r(vv.w);
                Vh[c4][r] = v0; Vh[c4 + 1][r] = v1; Vh[c4 + 2][r] = v2; Vh[c4 + 3][r] = v3;
                Vl[c4][r] = __float2bfloat16_rn(vv.x - v0);
                Vl[c4 + 1][r] = __float2bfloat16_rn(vv.y - v1);
                Vl[c4 + 2][r] = __float2bfloat16_rn(vv.z - v2);
                Vl[c4 + 3][r] = __float2bfloat16_rn(vv.w - v3);
            }
            __syncthreads();

            float s[4][4] = {};
            const int qr = 16 * wid + g;
#pragma unroll
            for (int kk = 0; kk < 4; kk++) {
                int k = kk * 8;
                unsigned ah[4], al[4];
                ah[0] = fu(Qh[qr][k + t4]);     ah[1] = fu(Qh[qr + 8][k + t4]);
                ah[2] = fu(Qh[qr][k + t4 + 4]); ah[3] = fu(Qh[qr + 8][k + t4 + 4]);
                al[0] = fu(b2f(Ql[qr][k + t4]));     al[1] = fu(b2f(Ql[qr + 8][k + t4]));
                al[2] = fu(b2f(Ql[qr][k + t4 + 4])); al[3] = fu(b2f(Ql[qr + 8][k + t4 + 4]));
#pragma unroll
                for (int ni = 0; ni < 4; ni++) {
                    int key = 8 * ni + g;
                    unsigned bh0 = fu(Kh[key][k + t4]), bh1 = fu(Kh[key][k + t4 + 4]);
                    mma8(s[ni], ah, bh0, bh1);
                    mma8(s[ni], ah, fu(b2f(Kl[key][k + t4])), fu(b2f(Kl[key][k + t4 + 4])));
                    mma8(s[ni], al, bh0, bh1);
                }
            }
#pragma unroll
            for (int ni = 0; ni < 4; ni++) {
                int col = kb + 8 * ni + 2 * t4;
                if (col >= c)     { s[ni][0] = -1e30f; s[ni][2] = -1e30f; }
                if (col + 1 >= c) { s[ni][1] = -1e30f; s[ni][3] = -1e30f; }
            }
            float mx1 = -1e30f, mx2 = -1e30f;
#pragma unroll
            for (int ni = 0; ni < 4; ni++) {
                mx1 = fmaxf(mx1, fmaxf(s[ni][0], s[ni][1]));
                mx2 = fmaxf(mx2, fmaxf(s[ni][2], s[ni][3]));
            }
            mx1 = fmaxf(mx1, __shfl_xor_sync(~0u, mx1, 1)); mx1 = fmaxf(mx1, __shfl_xor_sync(~0u, mx1, 2));
            mx2 = fmaxf(mx2, __shfl_xor_sync(~0u, mx2, 1)); mx2 = fmaxf(mx2, __shfl_xor_sync(~0u, mx2, 2));
            float nm1 = fmaxf(m1, mx1), nm2 = fmaxf(m2, mx2);
            float corr1 = __expf(m1 - nm1), corr2 = __expf(m2 - nm2);
            float sum1 = 0.f, sum2 = 0.f;
#pragma unroll
            for (int ni = 0; ni < 4; ni++) {
                float p0 = __expf(s[ni][0] - nm1), p1 = __expf(s[ni][1] - nm1);
                float p2 = __expf(s[ni][2] - nm2), p3 = __expf(s[ni][3] - nm2);
                sum1 += p0 + p1; sum2 += p2 + p3;
                int col = 8 * ni + 2 * t4;
                float r0 = tf32r(p0), r1 = tf32r(p1), r2 = tf32r(p2), r3 = tf32r(p3);
                Pm[wid][g][col] = r0;         Pm[wid][g][col + 1] = r1;
                Pm[wid][g + 8][col] = r2;     Pm[wid][g + 8][col + 1] = r3;
                Pl[wid][g][col] = __float2bfloat16_rn(p0 - r0);
                Pl[wid][g][col + 1] = __float2bfloat16_rn(p1 - r1);
                Pl[wid][g + 8][col] = __float2bfloat16_rn(p2 - r2);
                Pl[wid][g + 8][col + 1] = __float2bfloat16_rn(p3 - r3);
            }
            sum1 += __shfl_xor_sync(~0u, sum1, 1); sum1 += __shfl_xor_sync(~0u, sum1, 2);
            sum2 += __shfl_xor_sync(~0u, sum2, 1); sum2 += __shfl_xor_sync(~0u, sum2, 2);
            l1 = l1 * corr1 + sum1; l2 = l2 * corr2 + sum2;
#pragma unroll
            for (int nd = 0; nd < 4; nd++) {
                acc[nd][0] *= corr1; acc[nd][1] *= corr1;
                acc[nd][2] *= corr2; acc[nd][3] *= corr2;
            }
            m1 = nm1; m2 = nm2;
            __syncwarp();
#pragma unroll
            for (int kk = 0; kk < 4; kk++) {
                int k = kk * 8;
                unsigned ph[4], pl[4];
                ph[0] = fu(Pm[wid][g][k + t4]);     ph[1] = fu(Pm[wid][g + 8][k + t4]);
                ph[2] = fu(Pm[wid][g][k + t4 + 4]); ph[3] = fu(Pm[wid][g + 8][k + t4 + 4]);
                pl[0] = fu(b2f(Pl[wid][g][k + t4]));     pl[1] = fu(b2f(Pl[wid][g + 8][k + t4]));
                pl[2] = fu(b2f(Pl[wid][g][k + t4 + 4])); pl[3] = fu(b2f(Pl[wid][g + 8][k + t4 + 4]));
#pragma unroll
                for (int nd = 0; nd < 4; nd++) {
                    int d = 8 * nd + g;
                    unsigned vh0 = fu(Vh[d][k + t4]), vh1 = fu(Vh[d][k + t4 + 4]);
                    mma8(acc[nd], ph, vh0, vh1);
                    mma8(acc[nd], ph, fu(b2f(Vl[d][k + t4])), fu(b2f(Vl[d][k + t4 + 4])));
                    mma8(acc[nd], pl, vh0, vh1);
                }
            }
            __syncwarp();
        }

        if (npadf > 0.f) {
            const int qr = 16 * wid + g;
            float d1 = 0.f, d2 = 0.f;
#pragma unroll
            for (int j = 0; j < 8; j++) {
                int f = t4 * 8 + j;
                d1 += (Qh[qr][f] + b2f(Ql[qr][f])) * kp[f];
                d2 += (Qh[qr + 8][f] + b2f(Ql[qr + 8][f])) * kp[f];
            }
            d1 += __shfl_xor_sync(~0u, d1, 1); d1 += __shfl_xor_sync(~0u, d1, 2);
            d2 += __shfl_xor_sync(~0u, d2, 1); d2 += __shfl_xor_sync(~0u, d2, 2);
            float nm1 = fmaxf(m1, d1), nm2 = fmaxf(m2, d2);
            float corr1 = __expf(m1 - nm1), corr2 = __expf(m2 - nm2);
            float w1 = __expf(d1 - nm1) * npadf, w2 = __expf(d2 - nm2) * npadf;
            l1 = l1 * corr1 + w1; l2 = l2 * corr2 + w2;
#pragma unroll
            for (int nd = 0; nd < 4; nd++) {
                int d0 = 8 * nd + 2 * t4;
                acc[nd][0] = acc[nd][0] * corr1 + w1 * vp[d0];
                acc[nd][1] = acc[nd][1] * corr1 + w1 * vp[d0 + 1];
                acc[nd][2] = acc[nd][2] * corr2 + w2 * vp[d0];
                acc[nd][3] = acc[nd][3] * corr2 + w2 * vp[d0 + 1];
            }
        }
        float inv1 = 1.f / l1, inv2 = 1.f / l2;
        int row1 = q0 + 16 * wid + g, row2 = row1 + 8;
#pragma unroll
        for (int nd = 0; nd < 4; nd++) {
            int d0 = 8 * nd + 2 * t4;
            if (row1 < c)
                *(float2*)(g_ctx + (size_t)(start + row1) * 256 + h * HD + d0) =
                    make_float2(acc[nd][0] * inv1, acc[nd][1] * inv1);
            if (row2 < c)
                *(float2*)(g_ctx + (size_t)(start + row2) * 256 + h * HD + d0) =
                    make_float2(acc[nd][2] * inv2, acc[nd][3] * inv2);
        }
    }
}

// ---- BatchNorm + ReLU ----
__global__ void k_bn_stats()
{
    const int ch = threadIdx.x, r0 = blockIdx.x * 128;
    float s = 0.f, s2 = 0.f;
    for (int r = 0; r < 128; r++) {
        float v = g_att[(size_t)(r0 + r) * E + ch];
        s += v; s2 += v * v;
    }
    g_psum[blockIdx.x * E + ch] = s;
    g_psumsq[blockIdx.x * E + ch] = s2;
}
__global__ void k_bn_finalize(const float* __restrict__ gamma, const float* __restrict__ beta)
{
    const int ch = threadIdx.x;
    float s = 0.f, s2 = 0.f;
    for (int p = 0; p < 256; p++) { s += g_psum[p * E + ch]; s2 += g_psumsq[p * E + ch]; }
    float mean = s / (float)NN;
    float var = s2 / (float)NN - mean * mean;
    float sc = rsqrtf(var + BN_EPS) * gamma[ch];
    g_bnscale[ch] = sc;
    g_bnshift[ch] = beta[ch] - mean * sc;
}
__global__ void k_bn_apply(float* __restrict__ out)
{
    size_t idx = ((size_t)blockIdx.x * blockDim.x + threadIdx.x) * 4;
    int ch = (int)(idx & (E - 1));
    float4 v = *(const float4*)(g_att + idx);
    float4 r;
    r.x = fmaxf(v.x * g_bnscale[ch] + g_bnshift[ch], 0.f);
    r.y = fmaxf(v.y * g_bnscale[ch + 1] + g_bnshift[ch + 1], 0.f);
    r.z = fmaxf(v.z * g_bnscale[ch + 2] + g_bnshift[ch + 2], 0.f);
    r.w = fmaxf(v.w * g_bnscale[ch + 3] + g_bnshift[ch + 3], 0.f);
    *(float4*)(out + idx) = r;
}

extern "C" void kernel_launch(void* const* d_in, const int* in_sizes, int n_in,
                              void* d_out, int out_size)
{
    const float* x        = (const float*)d_in[0];
    const float* spectral = (const float*)d_in[1];
    const float* Ws       = (const float*)d_in[2];
    const float* bs       = (const float*)d_in[3];
    const float* W_in     = (const float*)d_in[4];
    const float* b_in     = (const float*)d_in[5];
    const float* W_out    = (const float*)d_in[6];
    const float* b_out    = (const float*)d_in[7];
    const float* gamma    = (const float*)d_in[8];
    const float* beta     = (const float*)d_in[9];
    const int*   batch32  = (const int*)d_in[10];
    float* out = (float*)d_out;

    k_detect<<<1, 256>>>(batch32);
    k_hist<<<NN / 256, 256>>>(batch32);
    k_scan<<<1, 1>>>();
    k_split_w<<<W_TOT / 256, 256>>>(W_in, W_out, Ws);

    k_gemm_scale_tc<<<NN / 64, 256>>>(x, spectral, bs);
    k_gemm_qkv_tc<<<dim3(NN / 64, 6), 256>>>(b_in);
    k_attn_tc<<<dim3(NB, NH), 128>>>(b_in);
    k_gemm_out_tc<<<dim3(NN / 64, 2), 256>>>(b_out);

    k_bn_stats<<<256, 256>>>();
    k_bn_finalize<<<1, 256>>>(gamma, beta);
    k_bn_apply<<<(NN * E / 4) / 256, 256>>>(out);
}

// round 10
// speedup vs baseline: 2.2133x; 1.3211x over previous
#include <cuda_runtime.h>
#include <cuda_bf16.h>

#define NN 32768
#define NB 64
#define E  256
#define NSC 4
#define NH 8
#define HD 32
#define BN_EPS 1e-5f

__device__ float g_h  [(size_t)NN * E];
__device__ float g_qkv[(size_t)NN * 3 * E];
__device__ float g_ctx[(size_t)NN * E];
__device__ float g_att[(size_t)NN * E];
__device__ int   g_counts[NB], g_starts[NB], g_maxM, g_stride;
__device__ float g_psum[256 * E], g_psumsq[256 * E];
__device__ float g_bnscale[E], g_bnshift[E];
#define W_TOT 327680            /* floats: W_in 196608 | W_out 65536 | Ws^T 65536 */
#define W_WORDS (W_TOT / 2)     /* packed bf16-pair words */
__device__ unsigned g_Whi[W_WORDS], g_Wlo[W_WORDS];

__device__ __forceinline__ unsigned short f2bs(float x)
{ return __bfloat16_as_ushort(__float2bfloat16_rn(x)); }
__device__ __forceinline__ float bs2f(unsigned short s)
{ return __bfloat162float(__ushort_as_bfloat16(s)); }
__device__ __forceinline__ float blo(unsigned u) { return bs2f((unsigned short)(u & 0xffff)); }
__device__ __forceinline__ float bhi(unsigned u) { return bs2f((unsigned short)(u >> 16)); }
// split (a,b) into packed bf16 hi-pair and lo-pair words
__device__ __forceinline__ void split2(float a, float b, unsigned& hi, unsigned& lo)
{
    unsigned short ha = f2bs(a), hb = f2bs(b);
    unsigned short la = f2bs(a - bs2f(ha)), lb = f2bs(b - bs2f(hb));
    hi = (unsigned)ha | ((unsigned)hb << 16);
    lo = (unsigned)la | ((unsigned)lb << 16);
}
__device__ __forceinline__ void mma16(float* c, const unsigned* a, unsigned b0, unsigned b1)
{
    asm volatile("mma.sync.aligned.m16n8k16.row.col.f32.bf16.bf16.f32 "
                 "{%0,%1,%2,%3}, {%4,%5,%6,%7}, {%8,%9}, {%0,%1,%2,%3};"
                 : "+f"(c[0]), "+f"(c[1]), "+f"(c[2]), "+f"(c[3])
                 : "r"(a[0]), "r"(a[1]), "r"(a[2]), "r"(a[3]), "r"(b0), "r"(b1));
}

// ---- batch bookkeeping (int32 vs int64 sniffing) ----
__global__ void k_detect(const int* __restrict__ b32)
{
    __shared__ int any;
    if (threadIdx.x == 0) any = 0;
    __syncthreads();
    int loc = 0;
    for (int i = threadIdx.x; i < NN / 2; i += blockDim.x)
        if (b32[2 * i + 1] != 0) loc = 1;
    if (loc) atomicExch(&any, 1);
    __syncthreads();
    if (threadIdx.x == 0) {
        g_stride = any ? 1 : 2;
        for (int b = 0; b < NB; b++) g_counts[b] = 0;
    }
}
__global__ void k_hist(const int* __restrict__ b32)
{
    __shared__ int hc[NB];
    int t = threadIdx.x;
    if (t < NB) hc[t] = 0;
    __syncthreads();
    int n = blockIdx.x * blockDim.x + t;
    atomicAdd(&hc[b32[(size_t)n * g_stride] & (NB - 1)], 1);
    __syncthreads();
    if (t < NB) atomicAdd(&g_counts[t], hc[t]);
}
__global__ void k_scan()
{
    int run = 0, mx = 0;
    for (int b = 0; b < NB; b++) {
        g_starts[b] = run;
        int c = g_counts[b];
        run += c;
        if (c > mx) mx = c;
    }
    g_maxM = mx;
}

// ---- weight split+pack prep: words of [W_in | W_out | Ws^T(s,o,k)] ----
__global__ void k_split_w(const float* __restrict__ W_in, const float* __restrict__ W_out,
                          const float* __restrict__ Ws)
{
    int i = blockIdx.x * blockDim.x + threadIdx.x;
    if (i >= W_WORDS) return;
    int e = 2 * i;
    float w0, w1;
    if (e < 196608) { w0 = W_in[e]; w1 = W_in[e + 1]; }
    else if (e < 262144) { w0 = W_out[e - 196608]; w1 = W_out[e - 196607]; }
    else {
        int j = e - 262144, s = j >> 14, rem = j & 16383;
        int o = rem >> 8, k = rem & 255;
        w0 = Ws[s * 16384 + k * 64 + o];
        w1 = Ws[s * 16384 + (k + 1) * 64 + o];
    }
    split2(w0, w1, g_Whi[i], g_Wlo[i]);
}

// ---- bf16x3 tensor-core GEMM body: C[NN,NTOT] = A[NN,256] * W^T + bias ----
// block 64m x 128n, 8 warps (4 wm x 2 wn), warp tile 16x64; k-chunks of 32
// (= 16 packed words, 2 x k16 mma steps). Device-global pointers bound by
// wrapper kernels in device code.
template<int NTOT>
__device__ __forceinline__ void gemm_tc_body(
    const float* __restrict__ A, const unsigned* __restrict__ Whi,
    const unsigned* __restrict__ Wlo, const float* __restrict__ bias,
    float* __restrict__ C)
{
    __shared__ unsigned Ah[64][20], Al[64][20];
    __shared__ unsigned Bh[128][20], Bl[128][20];
    const int tid = threadIdx.x, wid = tid >> 5, lane = tid & 31;
    const int g = lane >> 2, t4 = lane & 3, wm = wid >> 1, wn = wid & 1;
    const int m0 = blockIdx.x * 64, n0 = blockIdx.y * 128;

    float acc[8][4] = {};
    for (int ch = 0; ch < 8; ch++) {
        __syncthreads();
        for (int i = tid; i < 512; i += 256) {            // A chunk 64 x 32
            int r = i >> 3, fc = (i & 7) << 2, w0 = (i & 7) << 1;
            float4 v = *(const float4*)(A + (size_t)(m0 + r) * 256 + ch * 32 + fc);
            split2(v.x, v.y, Ah[r][w0], Al[r][w0]);
            split2(v.z, v.w, Ah[r][w0 + 1], Al[r][w0 + 1]);
        }
        for (int i = tid; i < 1024; i += 256) {           // B chunk 128 x 32 (words)
            int r = i >> 3, w2 = (i & 7) << 1;
            size_t go = (size_t)(n0 + r) * 128 + ch * 16 + w2;
            *(uint2*)&Bh[r][w2] = *(const uint2*)(Whi + go);
            *(uint2*)&Bl[r][w2] = *(const uint2*)(Wlo + go);
        }
        __syncthreads();
#pragma unroll
        for (int kk = 0; kk < 2; kk++) {
            const int kw = kk * 8, ra = 16 * wm + g;
            unsigned ah[4], al[4];
            ah[0] = Ah[ra][kw + t4];     ah[1] = Ah[ra + 8][kw + t4];
            ah[2] = Ah[ra][kw + t4 + 4]; ah[3] = Ah[ra + 8][kw + t4 + 4];
            al[0] = Al[ra][kw + t4];     al[1] = Al[ra + 8][kw + t4];
            al[2] = Al[ra][kw + t4 + 4]; al[3] = Al[ra + 8][kw + t4 + 4];
#pragma unroll
            for (int ni = 0; ni < 8; ni++) {
                int n = 64 * wn + 8 * ni + g;
                unsigned bh0 = Bh[n][kw + t4], bh1 = Bh[n][kw + t4 + 4];
                mma16(acc[ni], ah, bh0, bh1);
                mma16(acc[ni], ah, Bl[n][kw + t4], Bl[n][kw + t4 + 4]);
                mma16(acc[ni], al, bh0, bh1);
            }
        }
    }
    const int r1 = m0 + 16 * wm + g;
#pragma unroll
    for (int ni = 0; ni < 8; ni++) {
        int n = n0 + 64 * wn + 8 * ni + 2 * t4;
        float b0 = bias[n], b1 = bias[n + 1];
        *(float2*)(C + (size_t)r1 * NTOT + n)       = make_float2(acc[ni][0] + b0, acc[ni][1] + b1);
        *(float2*)(C + (size_t)(r1 + 8) * NTOT + n) = make_float2(acc[ni][2] + b0, acc[ni][3] + b1);
    }
}

__global__ void __launch_bounds__(256) k_gemm_qkv_tc(const float* __restrict__ bias)
{ gemm_tc_body<768>(g_h, g_Whi, g_Wlo, bias, g_qkv); }

__global__ void __launch_bounds__(256) k_gemm_out_tc(const float* __restrict__ bias)
{ gemm_tc_body<256>(g_ctx, g_Whi + 98304, g_Wlo + 98304, bias, g_att); }

// ---- scale GEMM: h[:, s*64+o] = (x + spec[s]) * WsT[s] + bs ----
__global__ void __launch_bounds__(256) k_gemm_scale_tc(
    const float* __restrict__ x, const float* __restrict__ spec,
    const float* __restrict__ bs)
{
    __shared__ unsigned Ah[64][20], Al[64][20];
    __shared__ unsigned Bh[64][20], Bl[64][20];
    const int tid = threadIdx.x, wid = tid >> 5, lane = tid & 31;
    const int g = lane >> 2, t4 = lane & 3, wm = wid >> 1, wn = wid & 1;
    const int m0 = blockIdx.x * 64;

    for (int s = 0; s < NSC; s++) {
        const float* sb = spec + (size_t)s * NN * 256;
        const unsigned* Wsh = g_Whi + 131072 + s * 8192;
        const unsigned* Wsl = g_Wlo + 131072 + s * 8192;
        float acc[4][4] = {};
        for (int ch = 0; ch < 8; ch++) {
            __syncthreads();
            for (int i = tid; i < 512; i += 256) {
                int r = i >> 3, fc = (i & 7) << 2, w0 = (i & 7) << 1;
                size_t go = (size_t)(m0 + r) * 256 + ch * 32 + fc;
                float4 a = *(const float4*)(x + go);
                float4 b = *(const float4*)(sb + go);
                a.x += b.x; a.y += b.y; a.z += b.z; a.w += b.w;
                split2(a.x, a.y, Ah[r][w0], Al[r][w0]);
                split2(a.z, a.w, Ah[r][w0 + 1], Al[r][w0 + 1]);
            }
            for (int i = tid; i < 512; i += 256) {
                int r = i >> 3, w2 = (i & 7) << 1;
                size_t go = (size_t)r * 128 + ch * 16 + w2;
                *(uint2*)&Bh[r][w2] = *(const uint2*)(Wsh + go);
                *(uint2*)&Bl[r][w2] = *(const uint2*)(Wsl + go);
            }
            __syncthreads();
#pragma unroll
            for (int kk = 0; kk < 2; kk++) {
                const int kw = kk * 8, ra = 16 * wm + g;
                unsigned ah[4], al[4];
                ah[0] = Ah[ra][kw + t4];     ah[1] = Ah[ra + 8][kw + t4];
                ah[2] = Ah[ra][kw + t4 + 4]; ah[3] = Ah[ra + 8][kw + t4 + 4];
                al[0] = Al[ra][kw + t4];     al[1] = Al[ra + 8][kw + t4];
                al[2] = Al[ra][kw + t4 + 4]; al[3] = Al[ra + 8][kw + t4 + 4];
#pragma unroll
                for (int ni = 0; ni < 4; ni++) {
                    int n = 32 * wn + 8 * ni + g;
                    unsigned bh0 = Bh[n][kw + t4], bh1 = Bh[n][kw + t4 + 4];
                    mma16(acc[ni], ah, bh0, bh1);
                    mma16(acc[ni], ah, Bl[n][kw + t4], Bl[n][kw + t4 + 4]);
                    mma16(acc[ni], al, bh0, bh1);
                }
            }
        }
        const int r1 = m0 + 16 * wm + g;
#pragma unroll
        for (int ni = 0; ni < 4; ni++) {
            int col = 32 * wn + 8 * ni + 2 * t4, n = s * 64 + col;
            float b0 = bs[n], b1 = bs[n + 1];
            *(float2*)(g_h + (size_t)r1 * 256 + n)       = make_float2(acc[ni][0] + b0, acc[ni][1] + b1);
            *(float2*)(g_h + (size_t)(r1 + 8) * 256 + n) = make_float2(acc[ni][2] + b0, acc[ni][3] + b1);
        }
        __syncthreads();
    }
}

// ---- flash attention (bf16x3 mma): 128 threads, Q tile 64, K/V tile 32 ----
// Pad keys of the reference (no key-padding mask) folded analytically with
// multiplicity (maxM - c).
__global__ void __launch_bounds__(128) k_attn_tc(const float* __restrict__ b_in)
{
    __shared__ unsigned      Qh[64][20], Ql[64][20];
    __shared__ unsigned      Kh[32][20], Kl[32][20];
    __shared__ __nv_bfloat16 Vh[32][40], Vl[32][40];   // d-major: [d][key]
    __shared__ unsigned      Pm[4][16][20], Pl[4][16][20];
    __shared__ float         kp[32], vp[32];

    const int b = blockIdx.x, h = blockIdx.y;
    const int tid = threadIdx.x, wid = tid >> 5, lane = tid & 31;
    const int g = lane >> 2, t4 = lane & 3;
    const int c = g_counts[b], start = g_starts[b];
    const float npadf = (float)(g_maxM - c);
    const float qs = 0.17677669529663687f;

    if (tid < 32) { kp[tid] = b_in[E + h * HD + tid]; vp[tid] = b_in[2 * E + h * HD + tid]; }

    for (int q0 = 0; q0 < c; q0 += 64) {
        __syncthreads();
        for (int i = tid; i < 512; i += 128) {            // Q tile 64 x 32
            int r = i >> 3, fc = (i & 7) << 2, w0 = (i & 7) << 1, row = q0 + r;
            float4 v = make_float4(0.f, 0.f, 0.f, 0.f);
            if (row < c) v = *(const float4*)(g_qkv + (size_t)(start + row) * 768 + h * HD + fc);
            v.x *= qs; v.y *= qs; v.z *= qs; v.w *= qs;
            split2(v.x, v.y, Qh[r][w0], Ql[r][w0]);
            split2(v.z, v.w, Qh[r][w0 + 1], Ql[r][w0 + 1]);
        }
        float m1 = -1e30f, m2 = -1e30f, l1 = 0.f, l2 = 0.f;
        float acc[4][4] = {};

        for (int kb = 0; kb < c; kb += 32) {
            __syncthreads();
            for (int i = tid; i < 256; i += 128) {        // K/V chunk 32 x 32
                int r = i >> 3, fc = (i & 7) << 2, w0 = (i & 7) << 1, key = kb + r;
                float4 kv = make_float4(0.f, 0.f, 0.f, 0.f);
                float4 vv = make_float4(0.f, 0.f, 0.f, 0.f);
                if (key < c) {
                    size_t base = (size_t)(start + key) * 768 + h * HD + fc;
                    kv = *(const float4*)(g_qkv + base + E);
                    vv = *(const float4*)(g_qkv + base + 2 * E);
                }
                split2(kv.x, kv.y, Kh[r][w0], Kl[r][w0]);
                split2(kv.z, kv.w, Kh[r][w0 + 1], Kl[r][w0 + 1]);
                float vs[4] = {vv.x, vv.y, vv.z, vv.w};
#pragma unroll
                for (int j = 0; j < 4; j++) {
                    __nv_bfloat16 hb = __float2bfloat16_rn(vs[j]);
                    Vh[fc + j][r] = hb;
                    Vl[fc + j][r] = __float2bfloat16_rn(vs[j] - __bfloat162float(hb));
                }
            }
            __syncthreads();

            float s[4][4] = {};
            const int qr = 16 * wid + g;
#pragma unroll
            for (int kk = 0; kk < 2; kk++) {
                const int kw = kk * 8;
                unsigned ah[4], al[4];
                ah[0] = Qh[qr][kw + t4];     ah[1] = Qh[qr + 8][kw + t4];
                ah[2] = Qh[qr][kw + t4 + 4]; ah[3] = Qh[qr + 8][kw + t4 + 4];
                al[0] = Ql[qr][kw + t4];     al[1] = Ql[qr + 8][kw + t4];
                al[2] = Ql[qr][kw + t4 + 4]; al[3] = Ql[qr + 8][kw + t4 + 4];
#pragma unroll
                for (int ni = 0; ni < 4; ni++) {
                    int key = 8 * ni + g;
                    unsigned bh0 = Kh[key][kw + t4], bh1 = Kh[key][kw + t4 + 4];
                    mma16(s[ni], ah, bh0, bh1);
                    mma16(s[ni], ah, Kl[key][kw + t4], Kl[key][kw + t4 + 4]);
                    mma16(s[ni], al, bh0, bh1);
                }
            }
#pragma unroll
            for (int ni = 0; ni < 4; ni++) {
                int col = kb + 8 * ni + 2 * t4;
                if (col >= c)     { s[ni][0] = -1e30f; s[ni][2] = -1e30f; }
                if (col + 1 >= c) { s[ni][1] = -1e30f; s[ni][3] = -1e30f; }
            }
            float mx1 = -1e30f, mx2 = -1e30f;
#pragma unroll
            for (int ni = 0; ni < 4; ni++) {
                mx1 = fmaxf(mx1, fmaxf(s[ni][0], s[ni][1]));
                mx2 = fmaxf(mx2, fmaxf(s[ni][2], s[ni][3]));
            }
            mx1 = fmaxf(mx1, __shfl_xor_sync(~0u, mx1, 1)); mx1 = fmaxf(mx1, __shfl_xor_sync(~0u, mx1, 2));
            mx2 = fmaxf(mx2, __shfl_xor_sync(~0u, mx2, 1)); mx2 = fmaxf(mx2, __shfl_xor_sync(~0u, mx2, 2));
            float nm1 = fmaxf(m1, mx1), nm2 = fmaxf(m2, mx2);
            float corr1 = __expf(m1 - nm1), corr2 = __expf(m2 - nm2);
            float sum1 = 0.f, sum2 = 0.f;
#pragma unroll
            for (int ni = 0; ni < 4; ni++) {
                float p0 = __expf(s[ni][0] - nm1), p1 = __expf(s[ni][1] - nm1);
                float p2 = __expf(s[ni][2] - nm2), p3 = __expf(s[ni][3] - nm2);
                sum1 += p0 + p1; sum2 += p2 + p3;
                int w = 4 * ni + t4;
                split2(p0, p1, Pm[wid][g][w], Pl[wid][g][w]);
                split2(p2, p3, Pm[wid][g + 8][w], Pl[wid][g + 8][w]);
            }
            sum1 += __shfl_xor_sync(~0u, sum1, 1); sum1 += __shfl_xor_sync(~0u, sum1, 2);
            sum2 += __shfl_xor_sync(~0u, sum2, 1); sum2 += __shfl_xor_sync(~0u, sum2, 2);
            l1 = l1 * corr1 + sum1; l2 = l2 * corr2 + sum2;
#pragma unroll
            for (int nd = 0; nd < 4; nd++) {
                acc[nd][0] *= corr1; acc[nd][1] *= corr1;
                acc[nd][2] *= corr2; acc[nd][3] *= corr2;
            }
            m1 = nm1; m2 = nm2;
            __syncwarp();
#pragma unroll
            for (int kk = 0; kk < 2; kk++) {
                const int kw = kk * 8;
                unsigned ph[4], pl[4];
                ph[0] = Pm[wid][g][kw + t4];     ph[1] = Pm[wid][g + 8][kw + t4];
                ph[2] = Pm[wid][g][kw + t4 + 4]; ph[3] = Pm[wid][g + 8][kw + t4 + 4];
                pl[0] = Pl[wid][g][kw + t4];     pl[1] = Pl[wid][g + 8][kw + t4];
                pl[2] = Pl[wid][g][kw + t4 + 4]; pl[3] = Pl[wid][g + 8][kw + t4 + 4];
#pragma unroll
                for (int nd = 0; nd < 4; nd++) {
                    int d = 8 * nd + g;
                    unsigned vh0 = *(const unsigned*)&Vh[d][2 * (kw + t4)];
                    unsigned vh1 = *(const unsigned*)&Vh[d][2 * (kw + t4 + 4)];
                    mma16(acc[nd], ph, vh0, vh1);
                    mma16(acc[nd], ph, *(const unsigned*)&Vl[d][2 * (kw + t4)],
                                       *(const unsigned*)&Vl[d][2 * (kw + t4 + 4)]);
                    mma16(acc[nd], pl, vh0, vh1);
                }
            }
            __syncwarp();
        }

        if (npadf > 0.f) {
            const int qr = 16 * wid + g;
            float d1 = 0.f, d2 = 0.f;
#pragma unroll
            for (int jw = 0; jw < 4; jw++) {
                int w = t4 + jw * 4;
                unsigned uh1 = Qh[qr][w], ul1 = Ql[qr][w];
                unsigned uh2 = Qh[qr + 8][w], ul2 = Ql[qr + 8][w];
                d1 += (blo(uh1) + blo(ul1)) * kp[2 * w] + (bhi(uh1) + bhi(ul1)) * kp[2 * w + 1];
                d2 += (blo(uh2) + blo(ul2)) * kp[2 * w] + (bhi(uh2) + bhi(ul2)) * kp[2 * w + 1];
            }
            d1 += __shfl_xor_sync(~0u, d1, 1); d1 += __shfl_xor_sync(~0u, d1, 2);
            d2 += __shfl_xor_sync(~0u, d2, 1); d2 += __shfl_xor_sync(~0u, d2, 2);
            float nm1 = fmaxf(m1, d1), nm2 = fmaxf(m2, d2);
            float corr1 = __expf(m1 - nm1), corr2 = __expf(m2 - nm2);
            float w1 = __expf(d1 - nm1) * npadf, w2 = __expf(d2 - nm2) * npadf;
            l1 = l1 * corr1 + w1; l2 = l2 * corr2 + w2;
#pragma unroll
            for (int nd = 0; nd < 4; nd++) {
                int d0 = 8 * nd + 2 * t4;
                acc[nd][0] = acc[nd][0] * corr1 + w1 * vp[d0];
                acc[nd][1] = acc[nd][1] * corr1 + w1 * vp[d0 + 1];
                acc[nd][2] = acc[nd][2] * corr2 + w2 * vp[d0];
                acc[nd][3] = acc[nd][3] * corr2 + w2 * vp[d0 + 1];
            }
        }
        float inv1 = 1.f / l1, inv2 = 1.f / l2;
        int row1 = q0 + 16 * wid + g, row2 = row1 + 8;
#pragma unroll
        for (int nd = 0; nd < 4; nd++) {
            int d0 = 8 * nd + 2 * t4;
            if (row1 < c)
                *(float2*)(g_ctx + (size_t)(start + row1) * 256 + h * HD + d0) =
                    make_float2(acc[nd][0] * inv1, acc[nd][1] * inv1);
            if (row2 < c)
                *(float2*)(g_ctx + (size_t)(start + row2) * 256 + h * HD + d0) =
                    make_float2(acc[nd][2] * inv2, acc[nd][3] * inv2);
        }
    }
}

// ---- BatchNorm + ReLU ----
__global__ void k_bn_stats()
{
    const int ch = threadIdx.x, r0 = blockIdx.x * 128;
    float s = 0.f, s2 = 0.f;
    for (int r = 0; r < 128; r++) {
        float v = g_att[(size_t)(r0 + r) * E + ch];
        s += v; s2 += v * v;
    }
    g_psum[blockIdx.x * E + ch] = s;
    g_psumsq[blockIdx.x * E + ch] = s2;
}
__global__ void k_bn_finalize(const float* __restrict__ gamma, const float* __restrict__ beta)
{
    const int ch = threadIdx.x;
    float s = 0.f, s2 = 0.f;
    for (int p = 0; p < 256; p++) { s += g_psum[p * E + ch]; s2 += g_psumsq[p * E + ch]; }
    float mean = s / (float)NN;
    float var = s2 / (float)NN - mean * mean;
    float sc = rsqrtf(var + BN_EPS) * gamma[ch];
    g_bnscale[ch] = sc;
    g_bnshift[ch] = beta[ch] - mean * sc;
}
__global__ void k_bn_apply(float* __restrict__ out)
{
    size_t idx = ((size_t)blockIdx.x * blockDim.x + threadIdx.x) * 4;
    int ch = (int)(idx & (E - 1));
    float4 v = *(const float4*)(g_att + idx);
    float4 r;
    r.x = fmaxf(v.x * g_bnscale[ch] + g_bnshift[ch], 0.f);
    r.y = fmaxf(v.y * g_bnscale[ch + 1] + g_bnshift[ch + 1], 0.f);
    r.z = fmaxf(v.z * g_bnscale[ch + 2] + g_bnshift[ch + 2], 0.f);
    r.w = fmaxf(v.w * g_bnscale[ch + 3] + g_bnshift[ch + 3], 0.f);
    *(float4*)(out + idx) = r;
}

extern "C" void kernel_launch(void* const* d_in, const int* in_sizes, int n_in,
                              void* d_out, int out_size)
{
    const float* x        = (const float*)d_in[0];
    const float* spectral = (const float*)d_in[1];
    const float* Ws       = (const float*)d_in[2];
    const float* bs       = (const float*)d_in[3];
    const float* W_in     = (const float*)d_in[4];
    const float* b_in     = (const float*)d_in[5];
    const float* W_out    = (const float*)d_in[6];
    const float* b_out    = (const float*)d_in[7];
    const float* gamma    = (const float*)d_in[8];
    const float* beta     = (const float*)d_in[9];
    const int*   batch32  = (const int*)d_in[10];
    float* out = (float*)d_out;

    k_detect<<<1, 256>>>(batch32);
    k_hist<<<NN / 256, 256>>>(batch32);
    k_scan<<<1, 1>>>();
    k_split_w<<<W_WORDS / 256, 256>>>(W_in, W_out, Ws);

    k_gemm_scale_tc<<<NN / 64, 256>>>(x, spectral, bs);
    k_gemm_qkv_tc<<<dim3(NN / 64, 6), 256>>>(b_in);
    k_attn_tc<<<dim3(NB, NH), 128>>>(b_in);
    k_gemm_out_tc<<<dim3(NN / 64, 2), 256>>>(b_out);

    k_bn_stats<<<256, 256>>>();
    k_bn_finalize<<<1, 256>>>(gamma, beta);
    k_bn_apply<<<(NN * E / 4) / 256, 256>>>(out);
}